// round 1
// baseline (speedup 1.0000x reference)
#include <cuda_runtime.h>
#include <cuda_bf16.h>

// Problem constants
#define D_MODEL   2048
#define NUM_HEADS 16
#define NUM_KVH   4
#define HEAD_DIM  128
#define KV_DIM    (NUM_KVH * HEAD_DIM)      // 512
#define QKV_COLS  (D_MODEL + 2 * KV_DIM)    // 3072
#define BATCH     2
#define SEQLEN    2048
#define ROWS      (BATCH * SEQLEN)          // 4096

// Scratch (no cudaMalloc allowed)
__device__ float g_qkv[ROWS * QKV_COLS];    // ~50 MB
__device__ float g_attn[ROWS * D_MODEL];    // ~33.5 MB

// ---------------------------------------------------------------------------
// SGEMM: C[M,N] = A[M,K] * B[K,N], all row-major. M%128==0, N%128==0, K%8==0.
// 128x128 block tile, BK=8, 8x8 per-thread microtile, 256 threads.
// ---------------------------------------------------------------------------
__global__ __launch_bounds__(256) void sgemm128(const float* __restrict__ A,
                                                const float* __restrict__ B,
                                                float* __restrict__ C,
                                                int M, int N, int K) {
    const int BM = 128, BN = 128, BK = 8, TM = 8, TN = 8;
    __shared__ float As[BK * BM];
    __shared__ float Bs[BK * BN];

    const int cCol = blockIdx.x;
    const int cRow = blockIdx.y;
    const int tid  = threadIdx.x;

    const int threadCol = tid % (BN / TN);  // 0..15
    const int threadRow = tid / (BN / TN);  // 0..15

    A += (long)cRow * BM * K;
    B += (long)cCol * BN;
    C += (long)cRow * BM * N + (long)cCol * BN;

    const int innerRowA = tid / (BK / 4);   // 0..127
    const int innerColA = tid % (BK / 4);   // 0..1
    const int innerRowB = tid / (BN / 4);   // 0..7
    const int innerColB = tid % (BN / 4);   // 0..31

    float acc[TM][TN];
#pragma unroll
    for (int i = 0; i < TM; i++)
#pragma unroll
        for (int j = 0; j < TN; j++) acc[i][j] = 0.0f;

    float regM[TM], regN[TN];

    for (int bk = 0; bk < K; bk += BK) {
        float4 ta = *reinterpret_cast<const float4*>(&A[(long)innerRowA * K + innerColA * 4]);
        As[(innerColA * 4 + 0) * BM + innerRowA] = ta.x;
        As[(innerColA * 4 + 1) * BM + innerRowA] = ta.y;
        As[(innerColA * 4 + 2) * BM + innerRowA] = ta.z;
        As[(innerColA * 4 + 3) * BM + innerRowA] = ta.w;
        *reinterpret_cast<float4*>(&Bs[innerRowB * BN + innerColB * 4]) =
            *reinterpret_cast<const float4*>(&B[(long)innerRowB * N + innerColB * 4]);
        __syncthreads();
        A += BK;
        B += (long)BK * N;
#pragma unroll
        for (int k = 0; k < BK; k++) {
#pragma unroll
            for (int i = 0; i < TM; i++) regM[i] = As[k * BM + threadRow * TM + i];
#pragma unroll
            for (int j = 0; j < TN; j++) regN[j] = Bs[k * BN + threadCol * TN + j];
#pragma unroll
            for (int i = 0; i < TM; i++)
#pragma unroll
                for (int j = 0; j < TN; j++) acc[i][j] += regM[i] * regN[j];
        }
        __syncthreads();
    }

#pragma unroll
    for (int i = 0; i < TM; i++) {
#pragma unroll
        for (int j = 0; j < TN; j += 4) {
            float4 v = make_float4(acc[i][j], acc[i][j + 1], acc[i][j + 2], acc[i][j + 3]);
            *reinterpret_cast<float4*>(
                &C[(long)(threadRow * TM + i) * N + threadCol * TN + j]) = v;
        }
    }
}

// ---------------------------------------------------------------------------
// RoPE applied in-place to q (16 heads) and k (4 heads) slices of g_qkv.
// One thread per (b, t, head, i) with i in [0,64).
// ---------------------------------------------------------------------------
__global__ void rope_kernel(float* __restrict__ qkv,
                            const float* __restrict__ sinp,
                            const float* __restrict__ cosp) {
    long idx = (long)blockIdx.x * blockDim.x + threadIdx.x;
    const long total = (long)ROWS * 20 * 64;  // 16 q heads + 4 k heads
    if (idx >= total) return;
    int i = idx & 63;
    long rest = idx >> 6;
    int head = (int)(rest % 20);
    long bt = rest / 20;            // 0..ROWS-1
    int t = (int)(bt % SEQLEN);

    int base = (head < 16) ? head * HEAD_DIM : D_MODEL + (head - 16) * HEAD_DIM;
    float* row = qkv + bt * QKV_COLS + base;
    float x1 = row[i];
    float x2 = row[i + 64];
    float s = sinp[t * 64 + i];
    float c = cosp[t * 64 + i];
    row[i]      = x1 * c - x2 * s;
    row[i + 64] = x2 * c + x1 * s;
}

// ---------------------------------------------------------------------------
// Flash attention, fp32, online softmax, causal + doc mask.
// grid = (S/64, B*NUM_HEADS), block = 256 threads.
// Per-thread: 4x4 score microtile, 4x8 output microtile.
// ---------------------------------------------------------------------------
#define BQ 64
#define BKV 64
#define QS_STRIDE 129
#define SS_STRIDE 65

__global__ __launch_bounds__(256) void flash_kernel(const float* __restrict__ qkv,
                                                    const int* __restrict__ doc_ids,
                                                    float* __restrict__ attn_out) {
    extern __shared__ float sm[];
    float* Qs = sm;                            // 64*129
    float* Ks = Qs + BQ * QS_STRIDE;           // 64*129
    float* Vs = Ks + BKV * QS_STRIDE;          // 64*129
    float* Ss = Vs + BKV * QS_STRIDE;          // 64*65
    float* m_s = Ss + BQ * SS_STRIDE;          // 64
    float* l_s = m_s + BQ;                     // 64
    float* al_s = l_s + BQ;                    // 64
    int* qdoc = (int*)(al_s + BQ);             // 64
    int* kdoc = qdoc + BQ;                     // 64

    const int qb = blockIdx.x;
    const int bh = blockIdx.y;
    const int b = bh >> 4;
    const int h = bh & 15;
    const int g = h >> 2;  // kv head
    const int tid = threadIdx.x;
    const int tr = tid >> 4;   // 0..15 -> rows 4*tr..4*tr+3
    const int tc = tid & 15;   // 0..15

    const int q0 = qb * BQ;
    const long rowbase = (long)b * SEQLEN * QKV_COLS;

    // Load Q tile, doc ids, init m/l
    for (int idx = tid; idx < BQ * HEAD_DIM; idx += 256) {
        int r = idx >> 7, d = idx & 127;
        Qs[r * QS_STRIDE + d] = qkv[rowbase + (long)(q0 + r) * QKV_COLS + h * HEAD_DIM + d];
    }
    if (tid < BQ) {
        qdoc[tid] = doc_ids[b * SEQLEN + q0 + tid];
        m_s[tid] = -1e30f;
        l_s[tid] = 0.0f;
    }

    float O[4][8];
#pragma unroll
    for (int i = 0; i < 4; i++)
#pragma unroll
        for (int j = 0; j < 8; j++) O[i][j] = 0.0f;

    const float scale = 0.08838834764831845f;  // 1/sqrt(128)

    for (int j0 = 0; j0 <= qb; ++j0) {
        const int k0 = j0 * BKV;
        for (int idx = tid; idx < BKV * HEAD_DIM; idx += 256) {
            int r = idx >> 7, d = idx & 127;
            long rrow = rowbase + (long)(k0 + r) * QKV_COLS;
            Ks[r * QS_STRIDE + d] = qkv[rrow + D_MODEL + g * HEAD_DIM + d];
            Vs[r * QS_STRIDE + d] = qkv[rrow + D_MODEL + KV_DIM + g * HEAD_DIM + d];
        }
        if (tid < BKV) kdoc[tid] = doc_ids[b * SEQLEN + k0 + tid];
        __syncthreads();

        // S = Q K^T (4x4 microtile)
        float acc[4][4];
#pragma unroll
        for (int i = 0; i < 4; i++)
#pragma unroll
            for (int j = 0; j < 4; j++) acc[i][j] = 0.0f;
        for (int k = 0; k < HEAD_DIM; ++k) {
            float qv[4], kv[4];
#pragma unroll
            for (int i = 0; i < 4; i++) qv[i] = Qs[(tr * 4 + i) * QS_STRIDE + k];
#pragma unroll
            for (int j = 0; j < 4; j++) kv[j] = Ks[(tc * 4 + j) * QS_STRIDE + k];
#pragma unroll
            for (int i = 0; i < 4; i++)
#pragma unroll
                for (int j = 0; j < 4; j++) acc[i][j] += qv[i] * kv[j];
        }
#pragma unroll
        for (int i = 0; i < 4; i++) {
            int qi = q0 + tr * 4 + i;
            int qd = qdoc[tr * 4 + i];
#pragma unroll
            for (int j = 0; j < 4; j++) {
                int ki = k0 + tc * 4 + j;
                bool ok = (ki <= qi) && (qd == kdoc[tc * 4 + j]);
                Ss[(tr * 4 + i) * SS_STRIDE + tc * 4 + j] = ok ? acc[i][j] * scale : -1e30f;
            }
        }
        __syncthreads();

        // Online softmax: 4 threads per row, 16 elems each
        {
            const int row = tid >> 2;
            const int qtr = tid & 3;
            float mx = -1e30f;
#pragma unroll
            for (int e = 0; e < 16; e++)
                mx = fmaxf(mx, Ss[row * SS_STRIDE + qtr * 16 + e]);
            mx = fmaxf(mx, __shfl_xor_sync(0xffffffffu, mx, 1));
            mx = fmaxf(mx, __shfl_xor_sync(0xffffffffu, mx, 2));
            float mold = m_s[row];
            float mnew = fmaxf(mold, mx);
            float alpha = __expf(mold - mnew);
            float sum = 0.0f;
#pragma unroll
            for (int e = 0; e < 16; e++) {
                float p = __expf(Ss[row * SS_STRIDE + qtr * 16 + e] - mnew);
                Ss[row * SS_STRIDE + qtr * 16 + e] = p;
                sum += p;
            }
            sum += __shfl_xor_sync(0xffffffffu, sum, 1);
            sum += __shfl_xor_sync(0xffffffffu, sum, 2);
            if (qtr == 0) {
                m_s[row] = mnew;
                l_s[row] = l_s[row] * alpha + sum;
                al_s[row] = alpha;
            }
        }
        __syncthreads();

        // O = O*alpha + P @ V  (4 rows x 8 cols per thread)
        float al[4];
#pragma unroll
        for (int i = 0; i < 4; i++) al[i] = al_s[tr * 4 + i];
#pragma unroll
        for (int i = 0; i < 4; i++)
#pragma unroll
            for (int j = 0; j < 8; j++) O[i][j] *= al[i];
        for (int kv = 0; kv < BKV; ++kv) {
            float pv[4], vv[8];
#pragma unroll
            for (int i = 0; i < 4; i++) pv[i] = Ss[(tr * 4 + i) * SS_STRIDE + kv];
#pragma unroll
            for (int j = 0; j < 8; j++) vv[j] = Vs[kv * QS_STRIDE + tc * 8 + j];
#pragma unroll
            for (int i = 0; i < 4; i++)
#pragma unroll
                for (int j = 0; j < 8; j++) O[i][j] += pv[i] * vv[j];
        }
        __syncthreads();  // protect Ks/Vs/Ss for next iter
    }

    // Finalize: divide by l, write out (attn layout [B*S, 2048], head h at col h*128)
#pragma unroll
    for (int i = 0; i < 4; i++) {
        float inv = 1.0f / l_s[tr * 4 + i];
        int qi = q0 + tr * 4 + i;
        long orow = (long)(b * SEQLEN + qi) * D_MODEL + h * HEAD_DIM;
#pragma unroll
        for (int j = 0; j < 8; j++) attn_out[orow + tc * 8 + j] = O[i][j] * inv;
    }
}

// ---------------------------------------------------------------------------
// Launch
// ---------------------------------------------------------------------------
extern "C" void kernel_launch(void* const* d_in, const int* in_sizes, int n_in,
                              void* d_out, int out_size) {
    const float* x     = (const float*)d_in[0];
    const float* sinp  = (const float*)d_in[1];
    const float* cosp  = (const float*)d_in[2];
    const int*   doc   = (const int*)d_in[3];
    const float* W_qkv = (const float*)d_in[4];
    const float* W_o   = (const float*)d_in[5];
    float* out = (float*)d_out;

    float* qkv = nullptr;
    float* attn = nullptr;
    cudaGetSymbolAddress((void**)&qkv, g_qkv);
    cudaGetSymbolAddress((void**)&attn, g_attn);

    // 1) QKV projection: [4096,2048] @ [2048,3072]
    {
        dim3 grid(QKV_COLS / 128, ROWS / 128);
        sgemm128<<<grid, 256>>>(x, W_qkv, qkv, ROWS, QKV_COLS, D_MODEL);
    }

    // 2) RoPE in-place on q,k
    {
        long total = (long)ROWS * 20 * 64;
        int blocks = (int)((total + 255) / 256);
        rope_kernel<<<blocks, 256>>>(qkv, sinp, cosp);
    }

    // 3) Flash attention
    {
        int smem = (3 * BQ * QS_STRIDE + BQ * SS_STRIDE + 3 * BQ) * sizeof(float)
                 + 2 * BQ * sizeof(int);
        cudaFuncSetAttribute(flash_kernel, cudaFuncAttributeMaxDynamicSharedMemorySize, smem);
        dim3 grid(SEQLEN / BQ, BATCH * NUM_HEADS);
        flash_kernel<<<grid, 256, smem>>>(qkv, doc, attn);
    }

    // 4) Output projection: [4096,2048] @ [2048,2048]
    {
        dim3 grid(D_MODEL / 128, ROWS / 128);
        sgemm128<<<grid, 256>>>(attn, W_o, out, ROWS, D_MODEL, D_MODEL);
    }
}

// round 4
// speedup vs baseline: 2.1090x; 2.1090x over previous
#include <cuda_runtime.h>
#include <cuda_bf16.h>
#include <cstdint>

// Problem constants
#define D_MODEL   2048
#define NUM_HEADS 16
#define NUM_KVH   4
#define HEAD_DIM  128
#define KV_DIM    (NUM_KVH * HEAD_DIM)      // 512
#define QKV_COLS  (D_MODEL + 2 * KV_DIM)    // 3072
#define BATCH     2
#define SEQLEN    2048
#define ROWS      (BATCH * SEQLEN)          // 4096

// Scratch (no cudaMalloc allowed)
__device__ float g_qkv[ROWS * QKV_COLS];    // ~50 MB
__device__ float g_attn[ROWS * D_MODEL];    // ~33.5 MB

// ---------------------------------------------------------------------------
// Helpers
// ---------------------------------------------------------------------------
__device__ __forceinline__ void cp_async16(void* smem, const void* gmem) {
    uint32_t s = (uint32_t)__cvta_generic_to_shared(smem);
    asm volatile("cp.async.cg.shared.global [%0], [%1], 16;\n" :: "r"(s), "l"(gmem));
}
__device__ __forceinline__ void cp_commit() { asm volatile("cp.async.commit_group;\n"); }
template <int N>
__device__ __forceinline__ void cp_wait() { asm volatile("cp.async.wait_group %0;\n" :: "n"(N)); }

__device__ __forceinline__ void mma_tf32(float* d, const uint32_t* a, const uint32_t* b) {
    asm volatile(
        "mma.sync.aligned.m16n8k8.row.col.f32.tf32.tf32.f32 "
        "{%0,%1,%2,%3},{%4,%5,%6,%7},{%8,%9},{%0,%1,%2,%3};\n"
        : "+f"(d[0]), "+f"(d[1]), "+f"(d[2]), "+f"(d[3])
        : "r"(a[0]), "r"(a[1]), "r"(a[2]), "r"(a[3]), "r"(b[0]), "r"(b[1]));
}

// Round-to-nearest fp32 -> tf32 (bits in a b32 register; low 13 bits zero).
__device__ __forceinline__ uint32_t f2tf32_rn(float f) {
    uint32_t r;
    asm("cvt.rn.tf32.f32 %0, %1;\n" : "=r"(r) : "f"(f));
    return r;
}
__device__ __forceinline__ float round_tf32(float f) {
    return __uint_as_float(f2tf32_rn(f));
}
// Split fp32 into tf32 hi (exact truncation) + tf32 lo (RN of residual).
__device__ __forceinline__ void split_tf32(float f, uint32_t& hi, uint32_t& lo) {
    uint32_t h = __float_as_uint(f) & 0xffffe000u;
    hi = h;
    lo = f2tf32_rn(f - __uint_as_float(h));
}

// ---------------------------------------------------------------------------
// 3xTF32 GEMM (near-fp32 accuracy): C = A * B, row-major.
// 128x128x16 block tile, 8 warps (32x64 warp tile), cp.async double buffer.
// Each k8 step issues 3 mmas per (mt,nt): a_hi*b_lo + a_lo*b_hi + a_hi*b_hi.
// ---------------------------------------------------------------------------
#define AS_STRIDE 20
#define BS_STRIDE 136

__global__ __launch_bounds__(256) void gemm_tf32x3(const float* __restrict__ A,
                                                   const float* __restrict__ B,
                                                   float* __restrict__ C,
                                                   int M, int N, int K) {
    __shared__ float As[2][128 * AS_STRIDE];
    __shared__ float Bs[2][16 * BS_STRIDE];

    const int tid = threadIdx.x;
    const int warp = tid >> 5, lane = tid & 31;
    const int g = lane >> 2, t4 = lane & 3;
    const int warpM = warp >> 1, warpN = warp & 1;
    const int m0 = blockIdx.y * 128, n0 = blockIdx.x * 128;

    float acc[2][8][4];
#pragma unroll
    for (int i = 0; i < 2; i++)
#pragma unroll
        for (int j = 0; j < 8; j++)
#pragma unroll
            for (int k = 0; k < 4; k++) acc[i][j][k] = 0.0f;

    auto load_tile = [&](int bk, int buf) {
#pragma unroll
        for (int c = tid; c < 512; c += 256) {  // A: 128 rows x 16 floats
            int row = c >> 2, kc = c & 3;
            cp_async16(&As[buf][row * AS_STRIDE + kc * 4],
                       &A[(long)(m0 + row) * K + bk + kc * 4]);
        }
#pragma unroll
        for (int c = tid; c < 512; c += 256) {  // B: 16 rows x 128 floats
            int k = c >> 5, nc = c & 31;
            cp_async16(&Bs[buf][k * BS_STRIDE + nc * 4],
                       &B[(long)(bk + k) * N + n0 + nc * 4]);
        }
    };

    load_tile(0, 0);
    cp_commit();
    const int KT = K / 16;
    for (int t = 0; t < KT; ++t) {
        int buf = t & 1;
        if (t + 1 < KT) {
            load_tile((t + 1) * 16, buf ^ 1);
            cp_commit();
            cp_wait<1>();
        } else {
            cp_wait<0>();
        }
        __syncthreads();
#pragma unroll
        for (int ks = 0; ks < 16; ks += 8) {
            uint32_t ah[2][4], al[2][4], bh[8][2], bl[8][2];
#pragma unroll
            for (int mt = 0; mt < 2; mt++) {
                int m = warpM * 32 + mt * 16;
                const float* ap = As[buf];
                split_tf32(ap[(m + g) * AS_STRIDE + ks + t4],         ah[mt][0], al[mt][0]);
                split_tf32(ap[(m + 8 + g) * AS_STRIDE + ks + t4],     ah[mt][1], al[mt][1]);
                split_tf32(ap[(m + g) * AS_STRIDE + ks + t4 + 4],     ah[mt][2], al[mt][2]);
                split_tf32(ap[(m + 8 + g) * AS_STRIDE + ks + t4 + 4], ah[mt][3], al[mt][3]);
            }
#pragma unroll
            for (int nt = 0; nt < 8; nt++) {
                int n = warpN * 64 + nt * 8;
                const float* bp = Bs[buf];
                split_tf32(bp[(ks + t4) * BS_STRIDE + n + g],     bh[nt][0], bl[nt][0]);
                split_tf32(bp[(ks + t4 + 4) * BS_STRIDE + n + g], bh[nt][1], bl[nt][1]);
            }
#pragma unroll
            for (int mt = 0; mt < 2; mt++)
#pragma unroll
                for (int nt = 0; nt < 8; nt++) {
                    mma_tf32(acc[mt][nt], ah[mt], bl[nt]);
                    mma_tf32(acc[mt][nt], al[mt], bh[nt]);
                    mma_tf32(acc[mt][nt], ah[mt], bh[nt]);
                }
        }
        __syncthreads();
    }

#pragma unroll
    for (int mt = 0; mt < 2; mt++)
#pragma unroll
        for (int nt = 0; nt < 8; nt++) {
            int m = m0 + warpM * 32 + mt * 16;
            int n = n0 + warpN * 64 + nt * 8 + 2 * t4;
            float2 v0 = {acc[mt][nt][0], acc[mt][nt][1]};
            float2 v1 = {acc[mt][nt][2], acc[mt][nt][3]};
            *(float2*)&C[(long)(m + g) * N + n] = v0;
            *(float2*)&C[(long)(m + 8 + g) * N + n] = v1;
        }
}

// ---------------------------------------------------------------------------
// RoPE in-place on q (16 heads) and k (4 heads) slices of g_qkv.
// ---------------------------------------------------------------------------
__global__ void rope_kernel(float* __restrict__ qkv,
                            const float* __restrict__ sinp,
                            const float* __restrict__ cosp) {
    long idx = (long)blockIdx.x * blockDim.x + threadIdx.x;
    const long total = (long)ROWS * 20 * 64;
    if (idx >= total) return;
    int i = idx & 63;
    long rest = idx >> 6;
    int head = (int)(rest % 20);
    long bt = rest / 20;
    int t = (int)(bt % SEQLEN);

    int base = (head < 16) ? head * HEAD_DIM : D_MODEL + (head - 16) * HEAD_DIM;
    float* row = qkv + bt * QKV_COLS + base;
    float x1 = row[i];
    float x2 = row[i + 64];
    float s = sinp[t * 64 + i];
    float c = cosp[t * 64 + i];
    row[i]      = x1 * c - x2 * s;
    row[i + 64] = x2 * c + x1 * s;
}

// ---------------------------------------------------------------------------
// Flash attention with RN-tf32 mma. All mma operands (Q,K,V,P) are rounded to
// tf32 with round-to-nearest ONCE at their smem write (kills truncation bias).
// ---------------------------------------------------------------------------
#define QK_STRIDE 132
#define V_STRIDE  136
#define S_STRIDE  68

__global__ __launch_bounds__(256) void flash_tf32(const float* __restrict__ qkv,
                                                  const int* __restrict__ doc_ids,
                                                  float* __restrict__ attn_out) {
    extern __shared__ float smf[];
    float* Qs = smf;                       // 64*132
    float* Ks = Qs + 64 * QK_STRIDE;       // 64*132
    float* Vs = Ks + 64 * QK_STRIDE;       // 64*136
    float* Ss = Vs + 64 * V_STRIDE;        // 64*68
    float* m_s = Ss + 64 * S_STRIDE;       // 64
    float* l_s = m_s + 64;                 // 64
    float* al_s = l_s + 64;                // 64
    int* qdoc = (int*)(al_s + 64);         // 64
    int* kdoc = qdoc + 64;                 // 64

    const int qb = blockIdx.x, bh = blockIdx.y;
    const int b = bh >> 4, h = bh & 15, gkv = h >> 2;
    const int tid = threadIdx.x, warp = tid >> 5, lane = tid & 31;
    const int g = lane >> 2, t4 = lane & 3;
    const int mi = warp >> 1, nh = warp & 1;
    const int q0 = qb * 64;
    const long rowbase = (long)b * SEQLEN * QKV_COLS;
    const float scale = 0.08838834764831845f;  // 1/sqrt(128)

    // Q tile (pre-scaled, RN-rounded to tf32), doc ids, running stats
    for (int idx = tid; idx < 64 * 128; idx += 256) {
        int r = idx >> 7, d = idx & 127;
        Qs[r * QK_STRIDE + d] = round_tf32(
            qkv[rowbase + (long)(q0 + r) * QKV_COLS + h * HEAD_DIM + d] * scale);
    }
    if (tid < 64) {
        qdoc[tid] = doc_ids[b * SEQLEN + q0 + tid];
        m_s[tid] = -1e30f;
        l_s[tid] = 0.0f;
    }

    float o[8][4];
#pragma unroll
    for (int i = 0; i < 8; i++)
#pragma unroll
        for (int j = 0; j < 4; j++) o[i][j] = 0.0f;

    for (int j0 = 0; j0 <= qb; ++j0) {
        const int k0 = j0 * 64;
        for (int idx = tid; idx < 64 * 128; idx += 256) {
            int r = idx >> 7, d = idx & 127;
            long rr = rowbase + (long)(k0 + r) * QKV_COLS + D_MODEL;
            Ks[r * QK_STRIDE + d] = round_tf32(qkv[rr + gkv * HEAD_DIM + d]);
            Vs[r * V_STRIDE + d]  = round_tf32(qkv[rr + KV_DIM + gkv * HEAD_DIM + d]);
        }
        if (tid < 64) kdoc[tid] = doc_ids[b * SEQLEN + k0 + tid];
        __syncthreads();

        // ---- S = Q K^T (tf32 mma), 4 n-tiles per warp ----
        float sacc[4][4];
#pragma unroll
        for (int i = 0; i < 4; i++)
#pragma unroll
            for (int j = 0; j < 4; j++) sacc[i][j] = 0.0f;

#pragma unroll
        for (int ks = 0; ks < 128; ks += 8) {
            uint32_t a[4];
            int m = mi * 16;
            a[0] = __float_as_uint(Qs[(m + g) * QK_STRIDE + ks + t4]);
            a[1] = __float_as_uint(Qs[(m + 8 + g) * QK_STRIDE + ks + t4]);
            a[2] = __float_as_uint(Qs[(m + g) * QK_STRIDE + ks + t4 + 4]);
            a[3] = __float_as_uint(Qs[(m + 8 + g) * QK_STRIDE + ks + t4 + 4]);
#pragma unroll
            for (int nt = 0; nt < 4; nt++) {
                int n = nh * 32 + nt * 8;
                uint32_t bb[2];
                bb[0] = __float_as_uint(Ks[(n + g) * QK_STRIDE + ks + t4]);
                bb[1] = __float_as_uint(Ks[(n + g) * QK_STRIDE + ks + t4 + 4]);
                mma_tf32(sacc[nt], a, bb);
            }
        }

        // ---- mask + write S to smem ----
        {
            int r1 = mi * 16 + g, r2 = r1 + 8;
            int qi1 = q0 + r1, qi2 = q0 + r2;
            int qd1 = qdoc[r1], qd2 = qdoc[r2];
#pragma unroll
            for (int nt = 0; nt < 4; nt++) {
                int cc = nh * 32 + nt * 8 + 2 * t4;
                int ki0 = k0 + cc, ki1 = ki0 + 1;
                int kd0 = kdoc[cc], kd1 = kdoc[cc + 1];
                float2 v1, v2;
                v1.x = (ki0 <= qi1 && kd0 == qd1) ? sacc[nt][0] : -1e30f;
                v1.y = (ki1 <= qi1 && kd1 == qd1) ? sacc[nt][1] : -1e30f;
                v2.x = (ki0 <= qi2 && kd0 == qd2) ? sacc[nt][2] : -1e30f;
                v2.y = (ki1 <= qi2 && kd1 == qd2) ? sacc[nt][3] : -1e30f;
                *(float2*)&Ss[r1 * S_STRIDE + cc] = v1;
                *(float2*)&Ss[r2 * S_STRIDE + cc] = v2;
            }
        }
        __syncthreads();

        // ---- online softmax: 4 threads per row; P stored RN-tf32 ----
        {
            const int row = tid >> 2, qtr = tid & 3;
            float mx = -1e30f;
#pragma unroll
            for (int e = 0; e < 16; e++) mx = fmaxf(mx, Ss[row * S_STRIDE + qtr * 16 + e]);
            mx = fmaxf(mx, __shfl_xor_sync(0xffffffffu, mx, 1));
            mx = fmaxf(mx, __shfl_xor_sync(0xffffffffu, mx, 2));
            float mold = m_s[row];
            float mnew = fmaxf(mold, mx);
            float sum = 0.0f;
#pragma unroll
            for (int e = 0; e < 16; e++) {
                float p = round_tf32(__expf(Ss[row * S_STRIDE + qtr * 16 + e] - mnew));
                Ss[row * S_STRIDE + qtr * 16 + e] = p;
                sum += p;
            }
            sum += __shfl_xor_sync(0xffffffffu, sum, 1);
            sum += __shfl_xor_sync(0xffffffffu, sum, 2);
            if (qtr == 0) {
                float alpha = __expf(mold - mnew);
                m_s[row] = mnew;
                l_s[row] = l_s[row] * alpha + sum;
                al_s[row] = alpha;
            }
        }
        __syncthreads();

        // ---- O = O*alpha + P @ V (tf32 mma), 8 n-tiles per warp ----
        {
            float alo = al_s[mi * 16 + g], ahi = al_s[mi * 16 + 8 + g];
#pragma unroll
            for (int nt = 0; nt < 8; nt++) {
                o[nt][0] *= alo; o[nt][1] *= alo;
                o[nt][2] *= ahi; o[nt][3] *= ahi;
            }
#pragma unroll
            for (int ks = 0; ks < 64; ks += 8) {
                uint32_t a[4];
                int m = mi * 16;
                a[0] = __float_as_uint(Ss[(m + g) * S_STRIDE + ks + t4]);
                a[1] = __float_as_uint(Ss[(m + 8 + g) * S_STRIDE + ks + t4]);
                a[2] = __float_as_uint(Ss[(m + g) * S_STRIDE + ks + t4 + 4]);
                a[3] = __float_as_uint(Ss[(m + 8 + g) * S_STRIDE + ks + t4 + 4]);
#pragma unroll
                for (int nt = 0; nt < 8; nt++) {
                    int n = nh * 64 + nt * 8;
                    uint32_t bb[2];
                    bb[0] = __float_as_uint(Vs[(ks + t4) * V_STRIDE + n + g]);
                    bb[1] = __float_as_uint(Vs[(ks + t4 + 4) * V_STRIDE + n + g]);
                    mma_tf32(o[nt], a, bb);
                }
            }
        }
        __syncthreads();
    }

    // ---- finalize: divide by l, write out ----
    {
        float ilo = 1.0f / l_s[mi * 16 + g], ihi = 1.0f / l_s[mi * 16 + 8 + g];
        int r1 = mi * 16 + g, r2 = r1 + 8;
        long orow1 = (long)(b * SEQLEN + q0 + r1) * D_MODEL + h * HEAD_DIM;
        long orow2 = (long)(b * SEQLEN + q0 + r2) * D_MODEL + h * HEAD_DIM;
#pragma unroll
        for (int nt = 0; nt < 8; nt++) {
            int cc = nh * 64 + nt * 8 + 2 * t4;
            float2 v1 = {o[nt][0] * ilo, o[nt][1] * ilo};
            float2 v2 = {o[nt][2] * ihi, o[nt][3] * ihi};
            *(float2*)&attn_out[orow1 + cc] = v1;
            *(float2*)&attn_out[orow2 + cc] = v2;
        }
    }
}

// ---------------------------------------------------------------------------
// Launch
// ---------------------------------------------------------------------------
extern "C" void kernel_launch(void* const* d_in, const int* in_sizes, int n_in,
                              void* d_out, int out_size) {
    const float* x     = (const float*)d_in[0];
    const float* sinp  = (const float*)d_in[1];
    const float* cosp  = (const float*)d_in[2];
    const int*   doc   = (const int*)d_in[3];
    const float* W_qkv = (const float*)d_in[4];
    const float* W_o   = (const float*)d_in[5];
    float* out = (float*)d_out;

    float* qkv = nullptr;
    float* attn = nullptr;
    cudaGetSymbolAddress((void**)&qkv, g_qkv);
    cudaGetSymbolAddress((void**)&attn, g_attn);

    // 1) QKV projection: [4096,2048] @ [2048,3072] (3xTF32, near-fp32)
    {
        dim3 grid(QKV_COLS / 128, ROWS / 128);
        gemm_tf32x3<<<grid, 256>>>(x, W_qkv, qkv, ROWS, QKV_COLS, D_MODEL);
    }

    // 2) RoPE in-place on q,k
    {
        long total = (long)ROWS * 20 * 64;
        int blocks = (int)((total + 255) / 256);
        rope_kernel<<<blocks, 256>>>(qkv, sinp, cosp);
    }

    // 3) Flash attention (RN-tf32 mma)
    {
        int smem = (64 * QK_STRIDE * 2 + 64 * V_STRIDE + 64 * S_STRIDE + 3 * 64) * (int)sizeof(float)
                 + 2 * 64 * (int)sizeof(int);
        cudaFuncSetAttribute(flash_tf32, cudaFuncAttributeMaxDynamicSharedMemorySize, smem);
        dim3 grid(SEQLEN / 64, BATCH * NUM_HEADS);
        flash_tf32<<<grid, 256, smem>>>(qkv, doc, attn);
    }

    // 4) Output projection: [4096,2048] @ [2048,2048] (3xTF32)
    {
        dim3 grid(D_MODEL / 128, ROWS / 128);
        gemm_tf32x3<<<grid, 256>>>(attn, W_o, out, ROWS, D_MODEL, D_MODEL);
    }
}